// round 12
// baseline (speedup 1.0000x reference)
#include <cuda_runtime.h>

// Radon forward projection, phase-split + row-pair-float2 + packed-f32x2,
// SINGLE-LAUNCH: the phase-partial reduction is fused via a last-block ticket.
// out[b,a,s] = sum_t bilinear(imgs[b], x(s,t), y(s,t)),
// x = s*cos - t*sin + c ; y = s*sin + t*cos + c ; c = 127.5.
//
// Block = (b, angle-pair, phase), 6480 blocks, 512 threads (2 angles x 256
// detectors). Phase p owns y0i in a 31-row band (32 for p0). Tile rows are
// float2 ROW PAIRS -> 2x LDS.64 per sample. 73.5 KB dynamic smem -> 3 CTAs/SM.
// Inner loop uses sm_103a packed f32x2 (fma.rn.f32x2) — bitwise identical to
// the scalar fmaf pairs it replaces, so the exact ownership proof holds.
//
// Ownership is EXACT: band p owns yv = y+1 in [lo_p, hi_p), integer float
// bounds, monotone in t; conservative analytic entry/exit + exact scans ->
// branchless counted loop; exit-scan start clamped to txhi+1 so all counted
// iterations are in-band AND in-window (every smem access staged).
//
// Fused reduction: each of the 720 (b,pair) groups has 9 phase blocks. Every
// block stores its 512 partials, __threadfence(), then one thread takes an
// atomic ticket; the LAST block of the group sums the 9 partials in fixed
// p-order (deterministic) and writes out[bp*512+tid], then resets the ticket
// to 0 (graph-replay safe). One kernel launch per call -> ncu finally
// captures the phase kernel, and ~13us of launch/tail overhead disappears.

#define B_ 8
#define N_ 256
#define A_ 180

constexpr int PAIRS      = A_ / 2;            // 90
constexpr int BAND       = 31;
constexpr int PHASES     = 9;                 // ceil(257/31)
constexpr int STRIDE     = 287;               // float2 elements per tile row
constexpr int TROWS      = 32;                // row-pairs: covers BAND+1 rows
constexpr int SMEM_BYTES = TROWS * STRIDE * 8;    // 73,472 B -> 3 CTAs/SM
constexpr int NGROUP     = B_ * PAIRS;            // 720
constexpr int NBLK       = NGROUP * PHASES;       // 6480

__device__ float g_partial[NBLK * 512];       // 13.3 MB static scratch
__device__ int   g_ticket[NGROUP];            // zero-init; self-resetting

// ---- packed f32x2 helpers (sm_103a FFMA2/FADD2 via PTX) ----
typedef unsigned long long u64;
__device__ __forceinline__ u64 pk2(float lo, float hi) {
    u64 r; asm("mov.b64 %0, {%1, %2};" : "=l"(r) : "f"(lo), "f"(hi)); return r;
}
__device__ __forceinline__ void upk2(u64 v, float& lo, float& hi) {
    asm("mov.b64 {%0, %1}, %2;" : "=f"(lo), "=f"(hi) : "l"(v));
}
__device__ __forceinline__ u64 fma2(u64 a, u64 b, u64 c) {
    u64 d; asm("fma.rn.f32x2 %0, %1, %2, %3;" : "=l"(d) : "l"(a), "l"(b), "l"(c));
    return d;
}
__device__ __forceinline__ u64 add2(u64 a, u64 b) {
    u64 d; asm("add.rn.f32x2 %0, %1, %2;" : "=l"(d) : "l"(a), "l"(b));
    return d;
}

// Store partial, take the group ticket, and if this is the group's last
// block, reduce the 9 partials in fixed p-order and write the output.
__device__ __forceinline__ void finalize_group(
    float acc, int bp, int tid, float* __restrict__ out)
{
    __shared__ int is_last;
    const int blk0 = bp * PHASES;             // first block of this group
    g_partial[(blk0 + (blockIdx.x % PHASES)) * 512 + tid] = acc;
    __threadfence();                          // make partial visible pre-ticket
    __syncthreads();                          // all 512 stores done & fenced
    if (tid == 0) {
        int prev = atomicAdd(&g_ticket[bp], 1);
        is_last = (prev == PHASES - 1);
    }
    __syncthreads();
    if (!is_last) return;

    __threadfence();                          // acquire: see peers' partials
    const float* p = g_partial + blk0 * 512 + tid;
    float sum = 0.0f;
    #pragma unroll
    for (int k = 0; k < PHASES; ++k) sum += p[k * 512];   // fixed order
    out[bp * 512 + tid] = sum;                // == out[b][pr*2+al][s]
    if (tid == 0) g_ticket[bp] = 0;           // reset for next graph replay
}

__global__ __launch_bounds__(512, 3)
void radon_phase_kernel(const float* __restrict__ imgs,
                        const float* __restrict__ angles,
                        float* __restrict__ out)
{
    extern __shared__ float2 tile[];

    const int tid  = threadIdx.x;
    const int blk  = blockIdx.x;
    const int p    = blk % PHASES;
    const int bp   = blk / PHASES;            // b*PAIRS + pair
    const int b    = bp / PAIRS;
    const int pr   = bp - b * PAIRS;
    const int al   = tid >> 8;                // which angle of the pair
    const int warp = tid >> 5;
    const int lane = tid & 31;

    const float ang = angles[pr * 2 + al];
    const float ca  = cosf(ang);
    const float sa  = sinf(ang);
    const float sf  = (float)(tid & 255) - 127.5f;
    const float xs  = fmaf(sf, ca, 127.5f);
    const float xs5 = xs + 5.0f;              // guard-shifted x origin
    const float ys1 = fmaf(sf, sa, 127.5f) + 1.0f;   // guard-shifted y origin
    const float nsa = -sa;
    const bool  up  = (ca >= 0.0f);           // yv non-decreasing in t?

    // yv endpoints (same fmaf form as the loop) for exact band pre-check
    const float yA    = fmaf(-127.5f, ca, ys1);
    const float yB    = fmaf( 127.5f, ca, ys1);
    const float yvmin = fminf(yA, yB);
    const float yvmax = fmaxf(yA, yB);

    // Owned band in yv space: floor(yv) in [lo, hi-1].
    // p=0: y0i in [-1,30] -> yv in [0,32).
    // p>0: y0i in [31p, 31p+30] -> yv in [31p+1, 31p+32). Exact int bounds.
    const float lo = (p == 0) ? 0.0f : (float)(BAND * p + 1);
    const float hi = (float)(BAND * p + 32);

    // block-wide empty-band early out (skip staging entirely)
    const bool hit = (yvmax >= lo) & (yvmin < hi);
    if (!__syncthreads_or(hit)) {
        finalize_group(0.0f, bp, tid, out);
        return;
    }

    // ---- stage row-pair tile: tile[r][c] = (img[base+r][c-5], img[base+r+1][c-5])
    const int base = BAND * p - 1;            // image row of tile row r=0 (.x half)
    const float* __restrict__ img = imgs + b * N_ * N_;
    for (int r = warp; r < TROWS; r += 16) {
        const int ir0 = base + r;
        const int ir1 = ir0 + 1;
        const bool v0ok = (unsigned)ir0 < (unsigned)N_;
        const bool v1ok = (unsigned)ir1 < (unsigned)N_;
        const float* s0 = img + ir0 * N_;
        const float* s1 = img + ir1 * N_;
        float2* dst = tile + r * STRIDE;
        for (int c = lane; c < STRIDE; c += 32) {
            int ic = c - 5;
            bool cin = (unsigned)ic < (unsigned)N_;
            float v0 = (v0ok && cin) ? s0[ic] : 0.0f;
            float v1 = (v1ok && cin) ? s1[ic] : 0.0f;
            dst[c] = make_float2(v0, v1);
        }
    }
    __syncthreads();

    float acc = 0.0f;

    if (hit) {
        // analytic helpers (conservative only; exactness from scans)
        const float inv_ca = 1.0f / ((ca == 0.0f) ? 1e-30f : ca);
        const float inv_sa = 1.0f / ((sa == 0.0f) ? 1e-30f : sa);

        // x-window: x outside (-3,259) padded +-2 -> both sampled cols are
        // zero guards -> exactly 0. Inside: xv = x+5 in (-0.01, 266.01).
        float tca = (xs + 3.0f)   * inv_sa;
        float tcb = (xs - 259.0f) * inv_sa;
        const int txlo = (int)fmaxf(floorf(fminf(tca, tcb) + 127.5f) - 2.0f, 0.0f);
        const int txhi = (int)fminf(ceilf (fmaxf(tca, tcb) + 127.5f) + 2.0f, 255.0f);

        // conservative analytic entry (pad -2, never late), exact entry scan
        const float Lb = up ? lo : hi;
        float t_ent = fmaf(Lb - ys1, inv_ca, 127.5f);
        int t = max((int)fmaxf(fminf(floorf(t_ent) - 2.0f, 255.0f), 0.0f), txlo);
        float tf = (float)t - 127.5f;
        for (; t <= txhi; ++t, tf += 1.0f) {
            float yv = fmaf(tf, ca, ys1);
            if (up ? (yv >= lo) : (yv < hi)) break;
        }

        int n = 0;
        if (t <= txhi) {
            // conservative analytic exit (pad -2, never late), exact exit
            // scan; start clamped to txhi+1 (in float, before the int cast)
            // so a window-limited ray counts exactly txhi+1-t iterations.
            const float Ub = up ? hi : lo;
            float t_xt = fmaf(Ub - ys1, inv_ca, 127.5f);
            float te_f = fmaxf(fminf(floorf(t_xt) - 2.0f, (float)(txhi + 1)),
                               (float)t);
            int te = (int)te_f;
            float tfe = (float)te - 127.5f;
            for (; te <= txhi; ++te, tfe += 1.0f) {
                float yv = fmaf(tfe, ca, ys1);
                if (up ? (yv >= hi) : (yv < lo)) break;   // first t past band
            }
            n = te - t;     // owned iterations: t .. te-1 (in-band, in-window)
        }

        // fold the band row offset into the base pointer:
        // row index = floor(yv) - 31p; idx = (floor(yv)-31p)*287 + xi
        const u64* __restrict__ tb64 =
            reinterpret_cast<const u64*>(tile) - (BAND * p) * STRIDE;

        // packed constants
        const u64 CANSA = pk2(ca, nsa);       // (ca, -sa)
        const u64 YXS   = pk2(ys1, xs5);      // (y origin, x origin)
        const u64 ONE2  = pk2(1.0f, 1.0f);
        const u64 NEG1  = pk2(-1.0f, -1.0f);
        u64 tf2 = pk2(tf, tf);

        #pragma unroll 4
        for (int k = 0; k < n; ++k) {
            u64 yx = fma2(tf2, CANSA, YXS);   // (yv, xv) — bitwise == scalar
            float yv, xv; upk2(yx, yv, xv);
            float fy = truncf(yv);            // yv >= 0 in-band: trunc == floor
            float fx = truncf(xv);            // eps<0 -> col 0 zero guard
            u64 wyx = fma2(pk2(fy, fx), NEG1, yx);   // (wy, wx), exact
            float wy, wx; upk2(wyx, wy, wx);
            int idx = (int)fmaf(fy, (float)STRIDE, fx);   // exact (< 2^24)

            u64 v0 = tb64[idx];               // (a00, a10)
            u64 v1 = tb64[idx + 1];           // (a01, a11)

            u64 d = fma2(v0, NEG1, v1);       // (a01-a00, a11-a10)
            u64 h = fma2(pk2(wx, wx), d, v0); // (h0, h1)
            float h0, h1; upk2(h, h0, h1);
            acc += fmaf(wy, h1 - h0, h0);

            tf2 = add2(tf2, ONE2);
        }
    }

    finalize_group(acc, bp, tid, out);
}

extern "C" void kernel_launch(void* const* d_in, const int* in_sizes, int n_in,
                              void* d_out, int out_size)
{
    const float* imgs   = (const float*)d_in[0];
    const float* angles = (const float*)d_in[1];
    float*       out    = (float*)d_out;

    cudaFuncSetAttribute(radon_phase_kernel,
                         cudaFuncAttributeMaxDynamicSharedMemorySize, SMEM_BYTES);

    radon_phase_kernel<<<NBLK, 512, SMEM_BYTES>>>(imgs, angles, out);
}